// round 5
// baseline (speedup 1.0000x reference)
#include <cuda_runtime.h>
#include <math.h>

#define H 1024
#define V 50257
#define S 4096
#define NT 256
#define DRAIN_K 8          // max pool chunks per idle window
#define CHUNK 16           // rows per pool chunk

// ---------------- scratch (__device__ globals) ----------------
__device__ float g_gi[3 * H];
__device__ float g_gh[3 * H];
__device__ float g_h[H];
__device__ float g_vpart[32][H];
__device__ float g_v[H];
__device__ float g_scores[S];
__device__ float g_w[S];
__device__ float g_ctxpart[32][H];
__device__ float g_ctx[H];
__device__ float g_logh[V];
__device__ unsigned g_cnt = 0;
__device__ unsigned g_gen = 0;
__device__ unsigned g_rowctr = 0;

// ---------------- helpers ----------------
__device__ __forceinline__ float warp_sum(float v) {
#pragma unroll
    for (int o = 16; o; o >>= 1) v += __shfl_xor_sync(0xffffffffu, v, o);
    return v;
}

// software grid barrier (all blocks co-resident by occupancy-derived grid size)
__device__ __forceinline__ void grid_sync() {
    __syncthreads();
    if (threadIdx.x == 0) {
        __threadfence();
        unsigned gen = *(volatile unsigned*)&g_gen;
        if (atomicAdd(&g_cnt, 1u) == gridDim.x - 1) {
            g_cnt = 0;
            __threadfence();
            *(volatile unsigned*)&g_gen = gen + 1;
        } else {
            while (*(volatile unsigned*)&g_gen == gen) { }
        }
        __threadfence();
    }
    __syncthreads();
}

// one pool chunk: compute h-half of logits for CHUNK rows. hbuf = h in shared.
// returns false when pool exhausted.
__device__ __forceinline__ bool drain_chunk(const float* __restrict__ out_w,
                                            const float4* hbuf, int* s_base,
                                            int t, int warp, int lane) {
    if (t == 0) *s_base = (int)atomicAdd(&g_rowctr, CHUNK);
    __syncthreads();
    int rb = *s_base;
    __syncthreads();
    if (rb >= V) return false;
#pragma unroll
    for (int k = 0; k < CHUNK / 8; k++) {       // 8 warps x 2 rows
        int r = rb + warp * (CHUNK / 8) + k;
        if (r < V) {
            const float4* wr = reinterpret_cast<const float4*>(out_w + (long)r * (2 * H));
            float acc = 0.f;
#pragma unroll
            for (int it = 0; it < 8; it++) {
                float4 w = wr[it * 32 + lane];
                float4 c = hbuf[it * 32 + lane];
                acc += w.x * c.x + w.y * c.y + w.z * c.z + w.w * c.w;
            }
            acc = warp_sum(acc);
            if (!lane) g_logh[r] = acc;
        }
    }
    return true;
}

#define DRAIN_WINDOW()                                                        \
    {                                                                         \
        for (int k = 0; k < DRAIN_K; k++)                                     \
            if (!drain_chunk(out_w, sbuf4, &s_base, t, warp, lane)) break;    \
    }

// ---------------- persistent mega-kernel ----------------
__global__ void __launch_bounds__(NT, 3)
k_all(const int* __restrict__ word,
      const float* __restrict__ last_hidden,
      const float* __restrict__ enc,
      const float* __restrict__ emb,
      const float* __restrict__ w_ih,
      const float* __restrict__ w_hh,
      const float* __restrict__ b_ih,
      const float* __restrict__ b_hh,
      const float* __restrict__ attn_w,
      const float* __restrict__ out_w,
      const float* __restrict__ out_b,
      float* __restrict__ dout) {
    __shared__ float4 sbuf4[512];   // [0..255]: x / h ; [256..511]: h_prev / v / ctx
    __shared__ int s_base;
    float* sbuf = (float*)sbuf4;

    const int t = threadIdx.x;
    const int b = blockIdx.x;
    const int warp = t >> 5, lane = t & 31;
    const int nwarp = gridDim.x * (NT / 32);
    const int gw = b * (NT / 32) + warp;

    // ===== A: gates (all blocks)  gi = w_ih@x + b_ih ; gh = w_hh@h_prev + b_hh
    {
        const float* x = emb + (long)word[0] * H;
        sbuf4[t]       = reinterpret_cast<const float4*>(x)[t];
        sbuf4[256 + t] = reinterpret_cast<const float4*>(last_hidden)[t];
        __syncthreads();
        for (int r = gw; r < 6 * H; r += nwarp) {
            const float* W;
            const float4* vec4;
            float bias;
            float* out;
            if (r < 3 * H) {
                W = w_ih + (long)r * H; vec4 = sbuf4;        bias = b_ih[r]; out = &g_gi[r];
            } else {
                int rr = r - 3 * H;
                W = w_hh + (long)rr * H; vec4 = sbuf4 + 256; bias = b_hh[rr]; out = &g_gh[rr];
            }
            const float4* w4 = reinterpret_cast<const float4*>(W);
            float acc = 0.f;
#pragma unroll
            for (int it = 0; it < 8; it++) {
                float4 a = w4[it * 32 + lane];
                float4 v = vec4[it * 32 + lane];
                acc += a.x * v.x + a.y * v.y + a.z * v.z + a.w * v.w;
            }
            acc = warp_sum(acc);
            if (!lane) *out = acc + bias;
        }
    }
    grid_sync();

    // ===== B: GRU (blocks 0..3); block 0 resets the logits-h row pool
    if (b == 0 && t == 0) g_rowctr = 0;
    if (b < 4) {
        int i = b * NT + t;
        float hp = last_hidden[i];
        float r = 1.f / (1.f + expf(-(g_gi[i] + g_gh[i])));
        float z = 1.f / (1.f + expf(-(g_gi[H + i] + g_gh[H + i])));
        float n = tanhf(g_gi[2 * H + i] + r * g_gh[2 * H + i]);
        float h = (1.f - z) * n + z * hp;
        g_h[i] = h;
        dout[V + i] = h;
    }
    grid_sync();

    // all non-participant blocks cache h in shared for pool drains
    if (b >= 128) {
        sbuf4[t] = reinterpret_cast<const float4*>(g_h)[t];
        __syncthreads();
    }

    // ===== C: v partials (blocks 0..127); others drain logits-h pool
    if (b < 128) {
        int jc = b >> 2;
        int c = (b & 3) * NT + t;
        const float* base = attn_w + (long)(jc * 32) * H + c;
        float s = 0.f;
#pragma unroll 8
        for (int j = 0; j < 32; j++)
            s += base[(long)j * H] * g_h[jc * 32 + j];
        g_vpart[jc][c] = s;
    } else {
        DRAIN_WINDOW();
    }
    grid_sync();

    // ===== D: reduce v (blocks 0..3); others drain
    if (b < 4) {
        int c = b * NT + t;
        float s = 0.f;
#pragma unroll
        for (int j = 0; j < 32; j++) s += g_vpart[j][c];
        g_v[c] = s;
    } else if (b >= 128) {
        DRAIN_WINDOW();
    }
    grid_sync();

    // ===== E: scores[s] = enc[s].v (all blocks; v in sbuf[256..511])
    {
        sbuf4[256 + t] = reinterpret_cast<const float4*>(g_v)[t];
        __syncthreads();
        for (int s = gw; s < S; s += nwarp) {
            const float4* er = reinterpret_cast<const float4*>(enc + (long)s * H);
            float acc = 0.f;
#pragma unroll
            for (int it = 0; it < 8; it++) {
                float4 e = er[it * 32 + lane];
                float4 v = sbuf4[256 + it * 32 + lane];
                acc += e.x * v.x + e.y * v.y + e.z * v.z + e.w * v.w;
            }
            acc = warp_sum(acc);
            if (!lane) g_scores[s] = acc;
        }
    }
    grid_sync();

    // ===== F: softmax (block 0); others drain
    if (b == 0) {
        float x[16];
        float m = -INFINITY;
#pragma unroll
        for (int k = 0; k < 16; k++) {
            x[k] = g_scores[t + NT * k];
            m = fmaxf(m, x[k]);
        }
#pragma unroll
        for (int o = 16; o; o >>= 1) m = fmaxf(m, __shfl_xor_sync(0xffffffffu, m, o));
        if (!lane) sbuf[warp] = m;
        __syncthreads();
        if (warp == 0) {
            m = (lane < 8) ? sbuf[lane] : -INFINITY;
#pragma unroll
            for (int o = 4; o; o >>= 1) m = fmaxf(m, __shfl_xor_sync(0xffffffffu, m, o));
            if (!lane) sbuf[64] = m;
        }
        __syncthreads();
        m = sbuf[64];
        float e[16];
        float sum = 0.f;
#pragma unroll
        for (int k = 0; k < 16; k++) { e[k] = expf(x[k] - m); sum += e[k]; }
        sum = warp_sum(sum);
        __syncthreads();
        if (!lane) sbuf[warp] = sum;
        __syncthreads();
        if (warp == 0) {
            sum = (lane < 8) ? sbuf[lane] : 0.f;
#pragma unroll
            for (int o = 4; o; o >>= 1) sum += __shfl_xor_sync(0xffffffffu, sum, o);
            if (!lane) sbuf[64] = sum;
        }
        __syncthreads();
        float inv = 1.f / sbuf[64];
#pragma unroll
        for (int k = 0; k < 16; k++) {
            float wt = e[k] * inv;
            g_w[t + NT * k] = wt;
            dout[V + H + t + NT * k] = wt;
        }
        __syncthreads();
    } else if (b >= 128) {
        DRAIN_WINDOW();
    }
    grid_sync();

    // ===== G: ctx partials (blocks 0..127); others drain
    if (b < 128) {
        int sc = b >> 2;
        int c = (b & 3) * NT + t;
        const float* base = enc + (long)(sc * 128) * H + c;
        float acc = 0.f;
#pragma unroll 8
        for (int s = 0; s < 128; s++)
            acc += g_w[sc * 128 + s] * base[(long)s * H];
        g_ctxpart[sc][c] = acc;
    } else {
        DRAIN_WINDOW();
    }
    grid_sync();

    // ===== H: reduce ctx (blocks 0..3); others drain
    if (b < 4) {
        int c = b * NT + t;
        float s = 0.f;
#pragma unroll
        for (int j = 0; j < 32; j++) s += g_ctxpart[j][c];
        g_ctx[c] = s;
    } else if (b >= 128) {
        DRAIN_WINDOW();
    }
    grid_sync();

    // ===== I: finish pool (h-half), then ctx-half + combine
    {
        __syncthreads();
        sbuf4[t]       = reinterpret_cast<const float4*>(g_h)[t];
        sbuf4[256 + t] = reinterpret_cast<const float4*>(g_ctx)[t];
        __syncthreads();
        while (drain_chunk(out_w, sbuf4, &s_base, t, warp, lane)) { }
    }
    grid_sync();
    {
        for (int r = gw; r < V; r += nwarp) {
            // ctx-half: out_w[r][H : 2H]   (THE R4 BUG: was +256 floats, must be +H)
            const float4* wr = reinterpret_cast<const float4*>(out_w + (long)r * (2 * H) + H);
            float acc = 0.f;
#pragma unroll
            for (int it = 0; it < 8; it++) {
                float4 w = wr[it * 32 + lane];
                float4 c = sbuf4[256 + it * 32 + lane];
                acc += w.x * c.x + w.y * c.y + w.z * c.z + w.w * c.w;
            }
            acc = warp_sum(acc);
            if (!lane) dout[r] = g_logh[r] + acc + out_b[r];
        }
    }
}

// ---------------- launch ----------------
extern "C" void kernel_launch(void* const* d_in, const int* in_sizes, int n_in,
                              void* d_out, int out_size) {
    const int* word = (const int*)d_in[0];
    const float* last_hidden = (const float*)d_in[1];
    const float* enc = (const float*)d_in[2];
    const float* emb = (const float*)d_in[3];
    const float* w_ih = (const float*)d_in[4];
    const float* w_hh = (const float*)d_in[5];
    const float* b_ih = (const float*)d_in[6];
    const float* b_hh = (const float*)d_in[7];
    const float* attn_w = (const float*)d_in[8];
    // d_in[9] = attn_b : constant pre-softmax shift -> softmax-invariant, dropped
    const float* out_w = (const float*)d_in[10];
    const float* out_b = (const float*)d_in[11];
    float* dout = (float*)d_out;

    // occupancy-derived persistent grid (guarantees co-residency for grid barrier)
    static int nb = 0;
    if (!nb) {
        int dev = 0, sms = 0, per_sm = 0;
        cudaGetDevice(&dev);
        cudaDeviceGetAttribute(&sms, cudaDevAttrMultiProcessorCount, dev);
        cudaOccupancyMaxActiveBlocksPerMultiprocessor(&per_sm, k_all, NT, 0);
        nb = sms * per_sm;
        if (nb < 160) nb = 160;   // need >=129 for phase participation sets
    }

    k_all<<<nb, NT>>>(word, last_hidden, enc, emb, w_ih, w_hh, b_ih, b_hh,
                      attn_w, out_w, out_b, dout);
}

// round 6
// speedup vs baseline: 1.0469x; 1.0469x over previous
#include <cuda_runtime.h>
#include <math.h>

#define H 1024
#define V 50257
#define S 4096
#define NT 256

// ---------------- scratch (__device__ globals) ----------------
__device__ float g_gi[3 * H];
__device__ float g_gh[3 * H];
__device__ float g_h[H];
__device__ float g_vpart[32][H];
__device__ float g_v[H];
__device__ float g_scores[S];
__device__ float g_w[S];
__device__ float g_ctxpart[32][H];
__device__ float g_ctx[H];
__device__ unsigned g_cnt = 0;
__device__ unsigned g_gen = 0;

// ---------------- helpers ----------------
__device__ __forceinline__ float warp_sum(float v) {
#pragma unroll
    for (int o = 16; o; o >>= 1) v += __shfl_xor_sync(0xffffffffu, v, o);
    return v;
}

// software grid barrier (all blocks co-resident via occupancy-derived grid)
__device__ __forceinline__ void grid_sync() {
    __syncthreads();
    if (threadIdx.x == 0) {
        __threadfence();
        unsigned gen = *(volatile unsigned*)&g_gen;
        if (atomicAdd(&g_cnt, 1u) == gridDim.x - 1) {
            g_cnt = 0;
            __threadfence();
            *(volatile unsigned*)&g_gen = gen + 1;
        } else {
            while (*(volatile unsigned*)&g_gen == gen) { }
        }
        __threadfence();
    }
    __syncthreads();
}

// ---------------- kernel 1: the whole chain up to ctx (persistent) ----------------
__global__ void __launch_bounds__(NT, 3)
k_chain(const int* __restrict__ word,
        const float* __restrict__ last_hidden,
        const float* __restrict__ enc,
        const float* __restrict__ emb,
        const float* __restrict__ w_ih,
        const float* __restrict__ w_hh,
        const float* __restrict__ b_ih,
        const float* __restrict__ b_hh,
        const float* __restrict__ attn_w,
        float* __restrict__ dout) {
    __shared__ float4 sbuf4[512];
    float* sbuf = (float*)sbuf4;

    const int t = threadIdx.x;
    const int b = blockIdx.x;
    const int warp = t >> 5, lane = t & 31;
    const int nwarp = gridDim.x * (NT / 32);
    const int gw = b * (NT / 32) + warp;

    // ===== A: gates  gi = w_ih@x + b_ih ; gh = w_hh@h_prev + b_hh (all blocks)
    {
        const float* x = emb + (long)word[0] * H;
        sbuf4[t]       = reinterpret_cast<const float4*>(x)[t];
        sbuf4[256 + t] = reinterpret_cast<const float4*>(last_hidden)[t];
        __syncthreads();
        for (int r = gw; r < 6 * H; r += nwarp) {
            const float* W;
            const float4* vec4;
            float bias;
            float* out;
            if (r < 3 * H) {
                W = w_ih + (long)r * H; vec4 = sbuf4;        bias = b_ih[r]; out = &g_gi[r];
            } else {
                int rr = r - 3 * H;
                W = w_hh + (long)rr * H; vec4 = sbuf4 + 256; bias = b_hh[rr]; out = &g_gh[rr];
            }
            const float4* w4 = reinterpret_cast<const float4*>(W);
            float acc = 0.f;
#pragma unroll
            for (int it = 0; it < 8; it++) {
                float4 a = w4[it * 32 + lane];
                float4 v = vec4[it * 32 + lane];
                acc += a.x * v.x + a.y * v.y + a.z * v.z + a.w * v.w;
            }
            acc = warp_sum(acc);
            if (!lane) *out = acc + bias;
        }
    }
    grid_sync();

    // ===== B: GRU (blocks 0..3)
    if (b < 4) {
        int i = b * NT + t;
        float hp = last_hidden[i];
        float r = 1.f / (1.f + expf(-(g_gi[i] + g_gh[i])));
        float z = 1.f / (1.f + expf(-(g_gi[H + i] + g_gh[H + i])));
        float n = tanhf(g_gi[2 * H + i] + r * g_gh[2 * H + i]);
        float h = (1.f - z) * n + z * hp;
        g_h[i] = h;
        dout[V + i] = h;                      // hidden output
    }
    grid_sync();

    // ===== C: v partials  v[c] = sum_j attn_w[j][c]*h[j]  (blocks 0..127)
    if (b < 128) {
        int jc = b >> 2;
        int c = (b & 3) * NT + t;
        const float* base = attn_w + (long)(jc * 32) * H + c;
        float s = 0.f;
#pragma unroll 8
        for (int j = 0; j < 32; j++)
            s += base[(long)j * H] * g_h[jc * 32 + j];
        g_vpart[jc][c] = s;
    }
    grid_sync();

    // ===== D: reduce v (blocks 0..3)
    if (b < 4) {
        int c = b * NT + t;
        float s = 0.f;
#pragma unroll
        for (int j = 0; j < 32; j++) s += g_vpart[j][c];
        g_v[c] = s;
    }
    grid_sync();

    // ===== E: scores[s] = enc[s].v (all blocks; attn_b is softmax-invariant)
    {
        sbuf4[256 + t] = reinterpret_cast<const float4*>(g_v)[t];
        __syncthreads();
        for (int s = gw; s < S; s += nwarp) {
            const float4* er = reinterpret_cast<const float4*>(enc + (long)s * H);
            float acc = 0.f;
#pragma unroll
            for (int it = 0; it < 8; it++) {
                float4 e = er[it * 32 + lane];
                float4 v = sbuf4[256 + it * 32 + lane];
                acc += e.x * v.x + e.y * v.y + e.z * v.z + e.w * v.w;
            }
            acc = warp_sum(acc);
            if (!lane) g_scores[s] = acc;
        }
    }
    grid_sync();

    // ===== F: softmax over 4096 (block 0)
    if (b == 0) {
        float x[16];
        float m = -INFINITY;
#pragma unroll
        for (int k = 0; k < 16; k++) {
            x[k] = g_scores[t + NT * k];
            m = fmaxf(m, x[k]);
        }
#pragma unroll
        for (int o = 16; o; o >>= 1) m = fmaxf(m, __shfl_xor_sync(0xffffffffu, m, o));
        if (!lane) sbuf[warp] = m;
        __syncthreads();
        if (warp == 0) {
            m = (lane < 8) ? sbuf[lane] : -INFINITY;
#pragma unroll
            for (int o = 4; o; o >>= 1) m = fmaxf(m, __shfl_xor_sync(0xffffffffu, m, o));
            if (!lane) sbuf[64] = m;
        }
        __syncthreads();
        m = sbuf[64];
        float e[16];
        float sum = 0.f;
#pragma unroll
        for (int k = 0; k < 16; k++) { e[k] = expf(x[k] - m); sum += e[k]; }
        sum = warp_sum(sum);
        __syncthreads();
        if (!lane) sbuf[warp] = sum;
        __syncthreads();
        if (warp == 0) {
            sum = (lane < 8) ? sbuf[lane] : 0.f;
#pragma unroll
            for (int o = 4; o; o >>= 1) sum += __shfl_xor_sync(0xffffffffu, sum, o);
            if (!lane) sbuf[64] = sum;
        }
        __syncthreads();
        float inv = 1.f / sbuf[64];
#pragma unroll
        for (int k = 0; k < 16; k++) {
            float wt = e[k] * inv;
            g_w[t + NT * k] = wt;
            dout[V + H + t + NT * k] = wt;   // attn_weights output
        }
        __syncthreads();
    }
    grid_sync();

    // ===== G: ctx partials (blocks 0..127)
    if (b < 128) {
        int sc = b >> 2;
        int c = (b & 3) * NT + t;
        const float* base = enc + (long)(sc * 128) * H + c;
        float acc = 0.f;
#pragma unroll 8
        for (int s = 0; s < 128; s++)
            acc += g_w[sc * 128 + s] * base[(long)s * H];
        g_ctxpart[sc][c] = acc;
    }
    grid_sync();

    // ===== H: reduce ctx (blocks 0..3); kernel-end publishes to k_logits
    if (b < 4) {
        int c = b * NT + t;
        float s = 0.f;
#pragma unroll
        for (int j = 0; j < 32; j++) s += g_ctxpart[j][c];
        g_ctx[c] = s;
    }
}

// ---------------- kernel 2: logits (flat grid, max occupancy; 412MB stream) ----
// warp per row, 8 rows/block; this exact structure measured ~6.4 TB/s in R1.
__global__ void k_logits(const float* __restrict__ out_w,
                         const float* __restrict__ out_b,
                         float* __restrict__ dout) {
    __shared__ float4 cat[512]; // 2048 floats = [h | ctx]
    int t = threadIdx.x;
    cat[t] = reinterpret_cast<const float4*>(g_h)[t];
    cat[256 + t] = reinterpret_cast<const float4*>(g_ctx)[t];
    __syncthreads();

    int warp = t >> 5, lane = t & 31;
    int r = blockIdx.x * 8 + warp;
    if (r >= V) return;
    const float4* wr = reinterpret_cast<const float4*>(out_w + (long)r * (2 * H));
    float acc = 0.f;
#pragma unroll
    for (int it = 0; it < 16; it++) {
        float4 w = wr[it * 32 + lane];
        float4 c = cat[it * 32 + lane];
        acc += w.x * c.x + w.y * c.y + w.z * c.z + w.w * c.w;
    }
    acc = warp_sum(acc);
    if (!lane) dout[r] = acc + out_b[r];
}

// ---------------- launch ----------------
extern "C" void kernel_launch(void* const* d_in, const int* in_sizes, int n_in,
                              void* d_out, int out_size) {
    const int* word = (const int*)d_in[0];
    const float* last_hidden = (const float*)d_in[1];
    const float* enc = (const float*)d_in[2];
    const float* emb = (const float*)d_in[3];
    const float* w_ih = (const float*)d_in[4];
    const float* w_hh = (const float*)d_in[5];
    const float* b_ih = (const float*)d_in[6];
    const float* b_hh = (const float*)d_in[7];
    const float* attn_w = (const float*)d_in[8];
    // d_in[9] = attn_b : constant pre-softmax shift -> softmax-invariant, dropped
    const float* out_w = (const float*)d_in[10];
    const float* out_b = (const float*)d_in[11];
    float* dout = (float*)d_out;

    // occupancy-derived persistent grid for the barrier kernel
    static int nb = 0;
    if (!nb) {
        int dev = 0, sms = 0, per_sm = 0;
        cudaGetDevice(&dev);
        cudaDeviceGetAttribute(&sms, cudaDevAttrMultiProcessorCount, dev);
        cudaOccupancyMaxActiveBlocksPerMultiprocessor(&per_sm, k_chain, NT, 0);
        nb = sms * per_sm;
        if (nb < 160) nb = 160;   // phase participation sets need >=129
    }

    k_chain<<<nb, NT>>>(word, last_hidden, enc, emb, w_ih, w_hh, b_ih, b_hh,
                        attn_w, dout);
    k_logits<<<(V + 7) / 8, 256>>>(out_w, out_b, dout);
}